// round 1
// baseline (speedup 1.0000x reference)
#include <cuda_runtime.h>
#include <cstdint>

// Shapes (fixed by the problem definition)
#define N_ATOMS_MAX 50000
#define CDIM 64
#define ROW  (3 * CDIM)   // 192 floats per atom

// Scratch accumulator: segment-sum target (38.4 MB). Static __device__ per rules.
__device__ float g_agg[N_ATOMS_MAX * ROW];

// ---------------------------------------------------------------------------
// Kernel 1: zero the accumulator (float4 stores)
// ---------------------------------------------------------------------------
__global__ void zero_kernel(float4* p, int n4) {
    int i = blockIdx.x * blockDim.x + threadIdx.x;
    if (i < n4) p[i] = make_float4(0.f, 0.f, 0.f, 0.f);
}

// ---------------------------------------------------------------------------
// Kernel 2: per-pair gather + gate + scatter-reduce.
// 16 threads per pair; each thread owns 4 channels (float4).
//   ix[p,x,c] = (p3[j,x,c] + d3[p,x]) * i1[p,c]   -> red.add into g_agg[i,x,c]
// red.global.add.v4.f32 = 4-wide reduction, no return value.
// ---------------------------------------------------------------------------
__global__ void pair_kernel(const int* __restrict__ ind,
                            const float* __restrict__ p3,
                            const float* __restrict__ i1,
                            const float* __restrict__ d3,
                            float* __restrict__ agg,
                            int n_pairs)
{
    int t = blockIdx.x * blockDim.x + threadIdx.x;
    int pair = t >> 4;
    if (pair >= n_pairs) return;
    int lane = t & 15;                   // channel group: 4 channels each

    int ai = ind[2 * pair + 0];          // destination atom i
    int aj = ind[2 * pair + 1];          // source atom j

    float4 g = *reinterpret_cast<const float4*>(i1 + (size_t)pair * CDIM + lane * 4);

    float dv[3];
    dv[0] = d3[3 * pair + 0];
    dv[1] = d3[3 * pair + 1];
    dv[2] = d3[3 * pair + 2];

    const float4* pj = reinterpret_cast<const float4*>(p3 + (size_t)aj * ROW);
    float4*       pa = reinterpret_cast<float4*>(agg + (size_t)ai * ROW);

#pragma unroll
    for (int x = 0; x < 3; x++) {
        float4 v = pj[x * 16 + lane];
        float dx = dv[x];
        float r0 = (v.x + dx) * g.x;
        float r1 = (v.y + dx) * g.y;
        float r2 = (v.z + dx) * g.z;
        float r3 = (v.w + dx) * g.w;
        asm volatile("red.global.add.v4.f32 [%0], {%1, %2, %3, %4};"
                     :: "l"(pa + x * 16 + lane),
                        "f"(r0), "f"(r1), "f"(r2), "f"(r3)
                     : "memory");
    }
}

// ---------------------------------------------------------------------------
// Kernel 3: per-atom GEMM + self-dot epilogue.
//   p3_new[a,x,d] = sum_c agg[a,x,c] * W[d,c]
//   dotted[a,d]   = sum_x p3_new[a,x,d]^2
// 256 threads / block, 4 atoms / block (64 threads per atom, one thread per d).
// W staged in shared TRANSPOSED with +1 pad -> conflict-free reads sWT[c][d].
// agg rows staged in shared; reads within an atom's warp-half are broadcasts.
// ---------------------------------------------------------------------------
__global__ void gemm_kernel(const float* __restrict__ agg,
                            const float* __restrict__ W,
                            float* __restrict__ p3_new,
                            float* __restrict__ dotted,
                            int n_atoms)
{
    __shared__ float sWT[CDIM][CDIM + 1];   // sWT[c][d] = W[d,c]
    __shared__ float sA[4][ROW];

    int tid = threadIdx.x;                   // 0..255

    // stage W transposed
    for (int k = tid; k < CDIM * CDIM; k += 256) {
        int d = k >> 6, c = k & 63;
        sWT[c][d] = W[k];
    }

    int a0 = blockIdx.x * 4;
    // stage 4 agg rows
    for (int k = tid; k < 4 * ROW; k += 256) {
        int la = k / ROW;
        int e  = k - la * ROW;
        int a  = a0 + la;
        sA[la][e] = (a < n_atoms) ? agg[(size_t)a * ROW + e] : 0.f;
    }
    __syncthreads();

    int la = tid >> 6;       // local atom 0..3
    int d  = tid & 63;       // output channel
    int a  = a0 + la;
    if (a >= n_atoms) return;

    float dot = 0.f;
#pragma unroll
    for (int x = 0; x < 3; x++) {
        float s = 0.f;
#pragma unroll
        for (int c = 0; c < CDIM; c++) {
            s += sA[la][x * CDIM + c] * sWT[c][d];
        }
        p3_new[(size_t)a * ROW + x * CDIM + d] = s;
        dot += s * s;
    }
    dotted[(size_t)a * CDIM + d] = dot;
}

// ---------------------------------------------------------------------------
// Launch: inputs (metadata order): ind_2 [P,2] i32, p3 [A,3,64] f32,
// i1 [P,64] f32, d3 [P,3] f32, W [64,64] f32.
// Output: p3_new [A,3,64] then dotted [A,64], concatenated in d_out.
// ---------------------------------------------------------------------------
extern "C" void kernel_launch(void* const* d_in, const int* in_sizes, int n_in,
                              void* d_out, int out_size)
{
    const int*   ind = (const int*)  d_in[0];
    const float* p3  = (const float*)d_in[1];
    const float* i1  = (const float*)d_in[2];
    const float* d3  = (const float*)d_in[3];
    const float* W   = (const float*)d_in[4];

    int n_pairs = in_sizes[0] / 2;
    int n_atoms = in_sizes[1] / ROW;

    float* p3_new = (float*)d_out;
    float* dotted = (float*)d_out + (size_t)n_atoms * ROW;

    float* agg;
    cudaGetSymbolAddress((void**)&agg, g_agg);

    // 1) zero accumulator
    {
        int n4 = n_atoms * ROW / 4;
        int blk = 256;
        zero_kernel<<<(n4 + blk - 1) / blk, blk>>>((float4*)agg, n4);
    }

    // 2) pair scatter-reduce
    {
        int total = n_pairs * 16;
        int blk = 256;
        pair_kernel<<<(total + blk - 1) / blk, blk>>>(ind, p3, i1, d3, agg, n_pairs);
    }

    // 3) epilogue GEMM + dot
    {
        int blocks = (n_atoms + 3) / 4;
        gemm_kernel<<<blocks, 256>>>(agg, W, p3_new, dotted, n_atoms);
    }
}